// round 7
// baseline (speedup 1.0000x reference)
#include <cuda_runtime.h>
#include <cuda_bf16.h>
#include <math.h>

// ---------------- scratch (device globals; no allocation allowed) ----------
// Activations are bf16x2 "pair-planes": pair (ci, ci+8) within each 16-channel
// block; plane index pp = (ci/16)*8 + (ci%8). One uint32 per pixel per plane.
__device__ unsigned g_bufA[16777216];  // conv1 out (8,32pp,256,256) / pooled (8,64pp,128,128)
__device__ unsigned g_bufB[33554432];  // conv2 out (8,64pp,256,256)
__device__ unsigned g_bufC[16777216];  // conv3 out (8,128pp,128,128)
__device__ unsigned g_bufD[16777216];  // conv4 out sr pass (8,128pp,128,128)
__device__ unsigned g_wpk[524288];     // packed bf16 A-fragment weights
__device__ double g_acc[3];            // 0: mse, 1: ssim S sum, 2: perceptual

__global__ void zero_acc_kernel() {
    g_acc[0] = 0.0; g_acc[1] = 0.0; g_acc[2] = 0.0;
}

// ---------------- helpers ----------------
__device__ __forceinline__ float block_reduce_sum(float v, float* sh, int tid) {
    #pragma unroll
    for (int o = 16; o > 0; o >>= 1) v += __shfl_down_sync(0xffffffffu, v, o);
    if ((tid & 31) == 0) sh[tid >> 5] = v;
    __syncthreads();
    if (tid < 32) {
        v = (tid < 8) ? sh[tid] : 0.0f;
        #pragma unroll
        for (int o = 4; o > 0; o >>= 1) v += __shfl_down_sync(0xffffffffu, v, o);
    }
    return v;
}

__device__ __forceinline__ unsigned pack_bf2(float lo, float hi) {
    __nv_bfloat162 h = __floats2bfloat162_rn(lo, hi);
    return *(unsigned*)&h;
}
__device__ __forceinline__ float2 unpack_bf2(unsigned u) {
    __nv_bfloat162 h = *(__nv_bfloat162*)&u;
    return __bfloat1622float2(h);
}
__device__ __forceinline__ float bf16r(float x) {
    return __bfloat162float(__float2bfloat16_rn(x));
}

__device__ __forceinline__ void mma_bf16(float* c, const uint4 a, const uint2 b) {
    asm volatile(
        "mma.sync.aligned.m16n8k16.row.col.f32.bf16.bf16.f32 "
        "{%0,%1,%2,%3}, {%4,%5,%6,%7}, {%8,%9}, {%0,%1,%2,%3};"
        : "+f"(c[0]), "+f"(c[1]), "+f"(c[2]), "+f"(c[3])
        : "r"(a.x), "r"(a.y), "r"(a.z), "r"(a.w), "r"(b.x), "r"(b.y));
}

__device__ __forceinline__ void cp_async4(unsigned dst, const void* src, bool ok) {
    int sz = ok ? 4 : 0;
    asm volatile("cp.async.ca.shared.global [%0], [%1], 4, %2;"
                 :: "r"(dst), "l"(src), "r"(sz));
}
__device__ __forceinline__ void cp_async16(unsigned dst, const void* src) {
    asm volatile("cp.async.cg.shared.global [%0], [%1], 16;" :: "r"(dst), "l"(src));
}
__device__ __forceinline__ void cp_commit() {
    asm volatile("cp.async.commit_group;");
}
template<int N>
__device__ __forceinline__ void cp_wait() {
    asm volatile("cp.async.wait_group %0;" :: "n"(N));
}

// ---------------- MSE ----------------
__global__ void mse_kernel(const float* __restrict__ a, const float* __restrict__ b, int n) {
    __shared__ float sh[32];
    float s = 0.0f;
    for (int i = blockIdx.x * blockDim.x + threadIdx.x; i < n; i += gridDim.x * blockDim.x) {
        float d = a[i] - b[i];
        s = fmaf(d, d, s);
    }
    s = block_reduce_sum(s, sh, threadIdx.x);
    if (threadIdx.x == 0) atomicAdd(&g_acc[0], (double)s);
}

// ---------------- SSIM ----------------
__global__ void ssim_kernel(const float* __restrict__ x, const float* __restrict__ y) {
    __shared__ float sxt[22][23];
    __shared__ float syt[22][23];
    __shared__ float sh[32];
    int b = blockIdx.z;
    int gx0 = blockIdx.x * 16, gy0 = blockIdx.y * 16;
    const float* xb = x + (size_t)b * 65536;
    const float* yb = y + (size_t)b * 65536;
    int tid = threadIdx.y * 16 + threadIdx.x;
    for (int i = tid; i < 22 * 22; i += 256) {
        int rr = i / 22, cc = i - rr * 22;
        int gy = gy0 + rr, gx = gx0 + cc;
        float vx = 0.0f, vy = 0.0f;
        if (gy < 256 && gx < 256) { vx = xb[gy * 256 + gx]; vy = yb[gy * 256 + gx]; }
        sxt[rr][cc] = vx; syt[rr][cc] = vy;
    }
    __syncthreads();
    int i = gy0 + threadIdx.y, j = gx0 + threadIdx.x;
    float S = 0.0f;
    if (i < 250 && j < 250) {
        float sx = 0, sy = 0, sxx = 0, syy = 0, sxy = 0;
        #pragma unroll
        for (int dy = 0; dy < 7; dy++) {
            #pragma unroll
            for (int dx = 0; dx < 7; dx++) {
                float a = sxt[threadIdx.y + dy][threadIdx.x + dx];
                float c = syt[threadIdx.y + dy][threadIdx.x + dx];
                sx += a; sy += c;
                sxx = fmaf(a, a, sxx); syy = fmaf(c, c, syy); sxy = fmaf(a, c, sxy);
            }
        }
        const float inv = 1.0f / 49.0f;
        const float cn  = 49.0f / 48.0f;
        float ux = sx * inv, uy = sy * inv;
        float vx  = cn * (sxx * inv - ux * ux);
        float vy  = cn * (syy * inv - uy * uy);
        float vxy = cn * (sxy * inv - ux * uy);
        const float C1 = 1e-4f, C2 = 9e-4f;
        S = ((2.0f * ux * uy + C1) * (2.0f * vxy + C2)) /
            ((ux * ux + uy * uy + C1) * (vx + vy + C2));
    }
    float tot = block_reduce_sum(S, sh, tid);
    if (tid == 0) atomicAdd(&g_acc[1], (double)tot);
}

// ---------------- conv1: 1 -> 64 ch, relu, bf16 pair-plane output ----------
__global__ void conv1_kernel(const float* __restrict__ in, const float* __restrict__ w,
                             const float* __restrict__ bias, unsigned* __restrict__ out) {
    __shared__ float sw[576];
    __shared__ float sb[64];
    int tid = threadIdx.x;
    for (int i = tid; i < 576; i += 256) sw[i] = w[i];
    if (tid < 64) sb[tid] = bias[tid];
    __syncthreads();
    int g = blockIdx.x * 256 + tid;
    int x4 = (g & 63) * 4;
    int y  = (g >> 6) & 255;
    int b  = g >> 14;
    const float* ib = in + (size_t)b * 65536;
    float inp[3][6];
    #pragma unroll
    for (int dy = 0; dy < 3; dy++) {
        int gy = y - 1 + dy;
        #pragma unroll
        for (int c = 0; c < 6; c++) {
            int gx = x4 - 1 + c;
            inp[dy][c] = ((unsigned)gy < 256u && (unsigned)gx < 256u) ? ib[gy * 256 + gx] : 0.0f;
        }
    }
    for (int s = 0; s < 4; s++) {
        for (int c = 0; c < 8; c++) {
            int coL = 16 * s + c, coH = coL + 8;
            float al0 = sb[coL], al1 = al0, al2 = al0, al3 = al0;
            float ah0 = sb[coH], ah1 = ah0, ah2 = ah0, ah3 = ah0;
            #pragma unroll
            for (int k = 0; k < 9; k++) {
                int ky = k / 3, kx = k - ky * 3;
                float wl = sw[coL * 9 + k], wh = sw[coH * 9 + k];
                al0 = fmaf(inp[ky][0 + kx], wl, al0);
                al1 = fmaf(inp[ky][1 + kx], wl, al1);
                al2 = fmaf(inp[ky][2 + kx], wl, al2);
                al3 = fmaf(inp[ky][3 + kx], wl, al3);
                ah0 = fmaf(inp[ky][0 + kx], wh, ah0);
                ah1 = fmaf(inp[ky][1 + kx], wh, ah1);
                ah2 = fmaf(inp[ky][2 + kx], wh, ah2);
                ah3 = fmaf(inp[ky][3 + kx], wh, ah3);
            }
            uint4 v;
            v.x = pack_bf2(fmaxf(al0, 0.0f), fmaxf(ah0, 0.0f));
            v.y = pack_bf2(fmaxf(al1, 0.0f), fmaxf(ah1, 0.0f));
            v.z = pack_bf2(fmaxf(al2, 0.0f), fmaxf(ah2, 0.0f));
            v.w = pack_bf2(fmaxf(al3, 0.0f), fmaxf(ah3, 0.0f));
            *(uint4*)(out + ((size_t)(b * 32 + s * 8 + c) * 65536) + (size_t)y * 256 + x4) = v;
        }
    }
}

// ---------------- maxpool 2x2 on bf16x2 pair-planes ----------------
__global__ void pool_kernel(const unsigned* __restrict__ in, unsigned* __restrict__ out,
                            int PP, int Ho, int Wo) {
    int n = 8 * PP * Ho * Wo;
    int Wi = 2 * Wo;
    for (int i = blockIdx.x * blockDim.x + threadIdx.x; i < n; i += gridDim.x * blockDim.x) {
        int x = i % Wo;
        int y = (i / Wo) % Ho;
        int bc = i / (Wo * Ho);
        const unsigned* p = in + ((size_t)bc * 2 * Ho + 2 * y) * Wi + 2 * x;
        __nv_bfloat162 a = *(__nv_bfloat162*)&p[0];
        __nv_bfloat162 b = *(__nv_bfloat162*)&p[1];
        __nv_bfloat162 c = *(__nv_bfloat162*)&p[Wi];
        __nv_bfloat162 d = *(__nv_bfloat162*)&p[Wi + 1];
        __nv_bfloat162 m = __hmax2(__hmax2(a, b), __hmax2(c, d));
        out[i] = *(unsigned*)&m;
    }
}

// ---------------- weight pre-pack: bf16 m16n8k16 A-fragments ----------------
// idx within 512-u32 tap block: ((mw*2+f)*8+q)*16 + k4*4 + reg
// reg r: row = q + (r&1)*8 ; c = k4 + (r>>1)*4 ; ci_lo = step*16+c, ci_hi = +8
__global__ void pack_w_kernel(const float* __restrict__ w, unsigned* __restrict__ dst,
                              int Cin, int Cout) {
    int steps = Cin >> 4;
    int total = (Cout / 64) * steps * 4608;
    for (int idx = blockIdx.x * blockDim.x + threadIdx.x; idx < total;
         idx += gridDim.x * blockDim.x) {
        int reg = idx & 3;
        int k4  = (idx >> 2) & 3;
        int q   = (idx >> 4) & 7;
        int f   = (idx >> 7) & 1;
        int mw  = (idx >> 8) & 1;
        int tap = (idx >> 9) % 9;
        int rest = idx / 4608;
        int step = rest % steps;
        int cb   = rest / steps;
        int co = cb * 64 + mw * 32 + f * 16 + q + (reg & 1) * 8;
        int c  = k4 + (reg >> 1) * 4;
        int ci_lo = step * 16 + c;
        float lo = w[((size_t)co * Cin + ci_lo) * 9 + tap];
        float hi = w[((size_t)co * Cin + ci_lo + 8) * 9 + tap];
        dst[idx] = pack_bf2(lo, hi);
    }
}

// ---------------- tensor-core 3x3 SAME conv (bf16 m16n8k16) ----------------
// Block: 8 warps = 2(M:co) x 4(N:px). Block tile 64co x 256px; K=16 ci/step.
// SMEM input: [pixel][8 u32] ; in-pixel slot perm (c&3)*2+(c>>2) so the
// B fragment (units c=k4, c=k4+4) is one LDS.64.
template<int W>
__global__ __launch_bounds__(256, 2) void conv_mma(
    const unsigned* __restrict__ in, const unsigned* __restrict__ wpack,
    const float* __restrict__ bias,
    unsigned* __restrict__ out, const unsigned* __restrict__ ref,
    int Cin, int Cout, int mode)
{
    constexpr int H = W;
    constexpr int HW = W * W;
    constexpr int LW = (W == 256) ? 8 : 7;
    constexpr int NROWS = 256 / W;
    constexpr int SROWS = NROWS + 2;
    constexpr int SCOLS = W + 2;
    constexpr int NPIX  = SROWS * SCOLS;
    constexpr int SIN_U = NPIX * 8;          // u32 per input buffer
    constexpr int SW_U  = 9 * 512;           // u32 per weight buffer

    extern __shared__ unsigned smem_u[];
    unsigned* s_in = smem_u;                 // 2 buffers
    unsigned* s_w  = smem_u + 2 * SIN_U;     // 2 buffers
    __shared__ float s_red[32];

    int tid = threadIdx.x;
    int warp = tid >> 5;
    int lane = tid & 31;
    int q  = lane >> 2;
    int k4 = lane & 3;
    int mw = warp & 1;
    int nw = warp >> 1;
    int mwoff = mw * 32;
    int nwoff = nw * 64;

    int P0  = blockIdx.x * 256;
    int cb  = blockIdx.y;
    int co0 = cb * 64;
    int b   = blockIdx.z;
    int y0  = P0 >> LW;
    int steps = Cin >> 4;

    unsigned s_in_u = (unsigned)__cvta_generic_to_shared(s_in);
    unsigned s_w_u  = (unsigned)__cvta_generic_to_shared(s_w);

    int awb0 = ((mw * 2 + 0) * 8 + q) * 16 + k4 * 4;   // u32 offset
    int awb1 = awb0 + 128;                             // f=1

    int bb[8];
    #pragma unroll
    for (int nf = 0; nf < 8; nf++) {
        int base = nwoff + nf * 8;
        int ry   = base >> LW;
        int col  = base & (W - 1);
        bb[nf] = ((ry * SCOLS + col) + q) * 8 + 2 * k4;
    }

    float acc[2][8][4];
    #pragma unroll
    for (int f = 0; f < 2; f++)
        #pragma unroll
        for (int nf = 0; nf < 8; nf++)
            #pragma unroll
            for (int e = 0; e < 4; e++) acc[f][nf][e] = 0.0f;

    const unsigned* inb = in + (size_t)b * (Cin >> 1) * HW;
    const unsigned* wblk = wpack + (size_t)cb * steps * 4608;

    auto stage = [&](int step, int buf) {
        const unsigned* pbase = inb + (size_t)step * 8 * HW;
        unsigned ibase = s_in_u + buf * SIN_U * 4;
        #pragma unroll 4
        for (int i = tid; i < NPIX * 8; i += 256) {
            int p = i >> 3;
            int c = i & 7;
            int r = p / SCOLS, cc = p - r * SCOLS;
            int gy = y0 - 1 + r;
            int gx = cc - 1;
            bool ok = ((unsigned)gy < (unsigned)H) && ((unsigned)gx < (unsigned)W);
            const unsigned* src = pbase + (size_t)c * HW + (ok ? (gy * W + gx) : 0);
            int slot = ((c & 3) << 1) + (c >> 2);
            cp_async4(ibase + (unsigned)(p * 8 + slot) * 4, src, ok);
        }
        unsigned wbase = s_w_u + buf * SW_U * 4;
        const unsigned* wsrc = wblk + (size_t)step * 4608;
        #pragma unroll
        for (int i = tid; i < 1152; i += 256)
            cp_async16(wbase + (unsigned)i * 16, wsrc + i * 4);
    };

    stage(0, 0);
    cp_commit();

    for (int s = 0; s < steps; s++) {
        int cur = s & 1;
        if (s + 1 < steps) {
            stage(s + 1, cur ^ 1);
            cp_commit();
            cp_wait<1>();
        } else {
            cp_wait<0>();
        }
        __syncthreads();

        const unsigned* bin = s_in + cur * SIN_U;
        const unsigned* bw  = s_w  + cur * SW_U;

        #pragma unroll
        for (int tap = 0; tap < 9; tap++) {
            const int ky = tap / 3, kx = tap - ky * 3;
            const int toff = (ky * SCOLS + kx) * 8;
            uint4 af0 = *(const uint4*)(bw + tap * 512 + awb0);
            uint4 af1 = *(const uint4*)(bw + tap * 512 + awb1);
            #pragma unroll
            for (int nf = 0; nf < 8; nf++) {
                uint2 bv = *(const uint2*)(bin + bb[nf] + toff);
                mma_bf16(acc[0][nf], af0, bv);
                mma_bf16(acc[1][nf], af1, bv);
            }
        }
        __syncthreads();
    }

    // ---- epilogue: pair-plane bf16 outputs ----
    if (mode == 0) {
        #pragma unroll
        for (int f = 0; f < 2; f++) {
            int coL = co0 + mwoff + f * 16 + q;
            float bv0 = __ldg(&bias[coL]);
            float bv8 = __ldg(&bias[coL + 8]);
            int pp = ((co0 + mwoff + f * 16) >> 4) * 8 + q;
            unsigned* pl = out + (size_t)(b * (Cout >> 1) + pp) * HW + P0;
            #pragma unroll
            for (int nf = 0; nf < 8; nf++) {
                int np = nwoff + nf * 8 + 2 * k4;
                uint2 v;
                v.x = pack_bf2(fmaxf(acc[f][nf][0] + bv0, 0.0f),
                               fmaxf(acc[f][nf][2] + bv8, 0.0f));
                v.y = pack_bf2(fmaxf(acc[f][nf][1] + bv0, 0.0f),
                               fmaxf(acc[f][nf][3] + bv8, 0.0f));
                *(uint2*)(pl + np) = v;
            }
        }
    } else {
        float lsum = 0.0f;
        #pragma unroll
        for (int f = 0; f < 2; f++) {
            int coL = co0 + mwoff + f * 16 + q;
            float bv0 = __ldg(&bias[coL]);
            float bv8 = __ldg(&bias[coL + 8]);
            int pp = ((co0 + mwoff + f * 16) >> 4) * 8 + q;
            const unsigned* pl = ref + (size_t)(b * (Cout >> 1) + pp) * HW + P0;
            #pragma unroll
            for (int nf = 0; nf < 8; nf++) {
                int np = nwoff + nf * 8 + 2 * k4;
                uint2 rv = *(const uint2*)(pl + np);
                float2 r0 = unpack_bf2(rv.x);
                float2 r1 = unpack_bf2(rv.y);
                float d0 = bf16r(fmaxf(acc[f][nf][0] + bv0, 0.0f)) - r0.x;
                float d1 = bf16r(fmaxf(acc[f][nf][2] + bv8, 0.0f)) - r0.y;
                float d2 = bf16r(fmaxf(acc[f][nf][1] + bv0, 0.0f)) - r1.x;
                float d3 = bf16r(fmaxf(acc[f][nf][3] + bv8, 0.0f)) - r1.y;
                lsum = fmaf(d0, d0, lsum);
                lsum = fmaf(d1, d1, lsum);
                lsum = fmaf(d2, d2, lsum);
                lsum = fmaf(d3, d3, lsum);
            }
        }
        float tot = block_reduce_sum(lsum, s_red, tid);
        if (tid == 0) atomicAdd(&g_acc[2], (double)tot);
    }
}

// ---------------- finalize ----------------
__global__ void finalize_kernel(float* out, int out_size) {
    double mse    = g_acc[0] / 524288.0;
    double ssim_l = 1.0 - g_acc[1] / 500000.0;
    double perc   = g_acc[2] / 33554432.0;
    double total  = mse + 0.5 * ssim_l + 0.1 * perc;
    float vals[4] = {(float)total, (float)mse, (float)ssim_l, (float)perc};
    for (int i = 0; i < 4 && i < out_size; i++) out[i] = vals[i];
}

// ---------------- launcher ----------------
extern "C" void kernel_launch(void* const* d_in, const int* in_sizes, int n_in,
                              void* d_out, int out_size) {
    (void)in_sizes; (void)n_in;
    const float* sr = (const float*)d_in[0];
    const float* hr = (const float*)d_in[1];
    const float* w1 = (const float*)d_in[2];
    const float* b1 = (const float*)d_in[3];
    const float* w2 = (const float*)d_in[4];
    const float* b2 = (const float*)d_in[5];
    const float* w3 = (const float*)d_in[6];
    const float* b3 = (const float*)d_in[7];
    const float* w4 = (const float*)d_in[8];
    const float* b4 = (const float*)d_in[9];
    float* out = (float*)d_out;

    unsigned *A, *B, *C, *D, *WP;
    cudaGetSymbolAddress((void**)&A, g_bufA);
    cudaGetSymbolAddress((void**)&B, g_bufB);
    cudaGetSymbolAddress((void**)&C, g_bufC);
    cudaGetSymbolAddress((void**)&D, g_bufD);
    cudaGetSymbolAddress((void**)&WP, g_wpk);
    unsigned* WP2 = WP;             // 2*4*4608  = 36864 u32
    unsigned* WP3 = WP + 36864;     // 4*8*4608  = 147456 u32
    unsigned* WP4 = WP + 184320;    // 4*16*4608 = 294912 u32

    const int smem256 = (2 * (3 * 258 * 8) + 2 * 4608) * 4;   // 86400 B
    const int smem128 = (2 * (4 * 130 * 8) + 2 * 4608) * 4;   // 70144 B
    cudaFuncSetAttribute(conv_mma<256>, cudaFuncAttributeMaxDynamicSharedMemorySize, smem256);
    cudaFuncSetAttribute(conv_mma<128>, cudaFuncAttributeMaxDynamicSharedMemorySize, smem128);

    zero_acc_kernel<<<1, 1>>>();
    pack_w_kernel<<<144, 256>>>(w2, WP2, 64, 128);
    pack_w_kernel<<<576, 256>>>(w3, WP3, 128, 256);
    pack_w_kernel<<<1152, 256>>>(w4, WP4, 256, 256);

    mse_kernel<<<512, 256>>>(sr, hr, 524288);
    ssim_kernel<<<dim3(16, 16, 8), dim3(16, 16)>>>(sr, hr);

    for (int pass = 0; pass < 2; pass++) {
        const float* img = pass ? hr : sr;
        conv1_kernel<<<512, 256>>>(img, w1, b1, A);
        conv_mma<256><<<dim3(256, 2, 8), 256, smem256>>>(A, WP2, b2, B, nullptr, 64, 128, 0);
        pool_kernel<<<4096, 256>>>(B, A, 64, 128, 128);
        conv_mma<128><<<dim3(64, 4, 8), 256, smem128>>>(A, WP3, b3, C, nullptr, 128, 256, 0);
        if (pass == 0)
            conv_mma<128><<<dim3(64, 4, 8), 256, smem128>>>(C, WP4, b4, D, nullptr, 256, 256, 0);
        else
            conv_mma<128><<<dim3(64, 4, 8), 256, smem128>>>(C, WP4, b4, nullptr, D, 256, 256, 1);
    }

    finalize_kernel<<<1, 1>>>(out, out_size);
}